// round 1
// baseline (speedup 1.0000x reference)
#include <cuda_runtime.h>
#include <cstdint>

// Problem constants
#define BB   64
#define TT   2048
#define II   200
#define HH   100
#define G4   400   // 4*H

// Scratch: xg[t][b][j] (t-major so scan CTA b streams coalesced rows), ~210MB.
__device__ float g_xg[(size_t)TT * BB * G4];
// Transposed W_ih: Wt[k][j] = W_ih[j][k]  (200 x 400) for coalesced loads.
__device__ float g_Wt[II * G4];

// ---- packed fp32x2 FMA (FFMA2) ----------------------------------------
union f2u { float2 f; unsigned long long u; };
union f4u { float4 f; ulonglong2 u; };

__device__ __forceinline__ unsigned long long ffma2(unsigned long long a,
                                                    unsigned long long b,
                                                    unsigned long long c) {
    unsigned long long d;
    asm("fma.rn.f32x2 %0, %1, %2, %3;" : "=l"(d) : "l"(a), "l"(b), "l"(c));
    return d;
}

__device__ __forceinline__ float sig_(float x) {
    return __fdividef(1.0f, 1.0f + __expf(-x));
}
__device__ __forceinline__ float tanh_(float x) {
    // 2*sigmoid(2x)-1, accurate to ~1e-6 with __expf
    return __fdividef(2.0f, 1.0f + __expf(-2.0f * x)) - 1.0f;
}

// ---- kernel 0: transpose W_ih ------------------------------------------
__global__ void transpose_wih(const float* __restrict__ Wih) {
    int o = blockIdx.x * 256 + threadIdx.x;   // o = k*400 + j (coalesced write)
    if (o < II * G4) {
        int k = o / G4;
        int j = o - k * G4;
        g_Wt[o] = Wih[j * II + k];
    }
}

// ---- kernel 1: input projection ----------------------------------------
// xg[t][b][j] = sum_i x[b][t][i] * W_ih[j][i] + (b_ih[j]+b_hh[j])
// Tile: 32 timesteps (rows) x 400 cols per CTA. grid = (T/32, B).
#define R_TILE 32
#define XS_STRIDE 44   // padded row stride (floats); 44*4=176 is 16B aligned

__global__ __launch_bounds__(400, 2)
void proj_kernel(const float* __restrict__ x,
                 const float* __restrict__ bih,
                 const float* __restrict__ bhh) {
    __shared__ float xs[II * XS_STRIDE];   // xs[k][r], 35.2 KB

    const int b  = blockIdx.y;
    const int t0 = blockIdx.x * R_TILE;
    const int j  = threadIdx.x;            // 0..399

    // Stage x[b][t0:t0+32][0:200] (contiguous 6400 floats) transposed to xs[k][r]
    const float* xsrc = x + ((size_t)b * TT + t0) * II;
    for (int idx = j; idx < R_TILE * II; idx += 400) {
        int r = idx / II;
        int k = idx - r * II;
        xs[k * XS_STRIDE + r] = xsrc[idx];
    }
    __syncthreads();

    unsigned long long acc[R_TILE / 2];
    #pragma unroll
    for (int q = 0; q < R_TILE / 2; ++q) acc[q] = 0ULL;

    #pragma unroll 4
    for (int k = 0; k < II; ++k) {
        float w = g_Wt[k * G4 + j];        // coalesced, L2-resident
        f2u wv; wv.f.x = w; wv.f.y = w;
        const float4* hp = (const float4*)&xs[k * XS_STRIDE];
        #pragma unroll
        for (int q = 0; q < R_TILE / 4; ++q) {
            f4u v; v.f = hp[q];            // rows 4q..4q+3 (warp-broadcast LDS.128)
            acc[2 * q]     = ffma2(wv.u, v.u.x, acc[2 * q]);
            acc[2 * q + 1] = ffma2(wv.u, v.u.y, acc[2 * q + 1]);
        }
    }

    const float bias = bih[j] + bhh[j];
    #pragma unroll
    for (int r = 0; r < R_TILE; ++r) {
        f2u a; a.u = acc[r >> 1];
        float val = ((r & 1) ? a.f.y : a.f.x) + bias;
        g_xg[((size_t)(t0 + r) * BB + b) * G4 + j] = val;
    }
}

// ---- kernel 2: sequential LSTM scan ------------------------------------
// One CTA per batch row. 400 threads; thread j owns gate j.
// W_hh row j (100 floats) lives in registers; h lives in shared.
__global__ __launch_bounds__(400, 1)
void scan_kernel(const float* __restrict__ Whh, float* __restrict__ out) {
    const int b = blockIdx.x;
    const int j = threadIdx.x;

    __shared__ __align__(16) float h_sh[HH];
    __shared__ float a_sh[G4];

    // Load W_hh[j][0:100] into registers as 25 float4.
    f4u wreg[HH / 4];
    const float4* wr = (const float4*)(Whh + j * HH);
    #pragma unroll
    for (int q = 0; q < HH / 4; ++q) wreg[q].f = wr[q];

    float c = 0.0f;
    float hval = 0.0f;
    if (j < HH) h_sh[j] = 0.0f;
    __syncthreads();

    const float* xg = g_xg + (size_t)b * G4 + j;

    for (int t = 0; t < TT; ++t) {
        // prefetch this step's input-projection element (consumed ~300cyc later)
        float xv = xg[(size_t)t * (BB * G4)];

        unsigned long long acc0 = 0ULL, acc1 = 0ULL;
        #pragma unroll
        for (int q = 0; q < HH / 4; ++q) {
            f4u h4; h4.f = ((const float4*)h_sh)[q];   // broadcast LDS.128
            acc0 = ffma2(wreg[q].u.x, h4.u.x, acc0);
            acc1 = ffma2(wreg[q].u.y, h4.u.y, acc1);
        }
        f2u s0, s1; s0.u = acc0; s1.u = acc1;
        float gate = s0.f.x + s0.f.y + s1.f.x + s1.f.y + xv;

        // gate order i,f,g,o in chunks of 100; 'g' (200..299) uses tanh
        float a = (j >= 200 && j < 300) ? tanh_(gate) : sig_(gate);
        a_sh[j] = a;
        __syncthreads();

        if (j < HH) {
            float ig = a_sh[j];
            float fg = a_sh[HH + j];
            float gg = a_sh[2 * HH + j];
            float og = a_sh[3 * HH + j];
            c = fg * c + ig * gg;
            hval = og * tanh_(c);
            h_sh[j] = hval;
        }
        __syncthreads();
    }

    if (j < HH) out[b * HH + j] = hval;
}

// ---- launch ------------------------------------------------------------
extern "C" void kernel_launch(void* const* d_in, const int* in_sizes, int n_in,
                              void* d_out, int out_size) {
    const float* x    = (const float*)d_in[0];   // [64,2048,200]
    const float* Wih  = (const float*)d_in[1];   // [400,200]
    const float* Whh  = (const float*)d_in[2];   // [400,100]
    const float* bih  = (const float*)d_in[3];   // [400]
    const float* bhh  = (const float*)d_in[4];   // [400]
    float* out = (float*)d_out;                  // [64,100]

    transpose_wih<<<(II * G4 + 255) / 256, 256>>>(Wih);
    proj_kernel<<<dim3(TT / R_TILE, BB), 400>>>(x, bih, bhh);
    scan_kernel<<<BB, 400>>>(Whh, out);
}